// round 4
// baseline (speedup 1.0000x reference)
#include <cuda_runtime.h>
#include <cuda_bf16.h>
#include <mma.h>

using namespace nvcuda;

// Problem constants
#define T_TOK   2048
#define LM_DIM  4096
#define V_DIM   1024
#define N_V     32
#define FF      1024
#define VIS_K   (V_DIM * N_V)        // 32768
#define IN_DIM  (VIS_K + LM_DIM)     // 36864
#define B_SAMP  16
#define OUT_D   6

#define KSPLIT  64
#define KCHUNK  (VIS_K / KSPLIT)     // 512

// Scratch (static device globals: allocation-free rule)
__device__ float g_V1part[KSPLIT * B_SAMP * FF];   // 4 MB
__device__ float g_V1[B_SAMP * FF];                // 64 KB
__device__ float g_HA[T_TOK * FF];                 // 8 MB
__device__ float g_HB[T_TOK * FF];                 // 8 MB
__device__ int   g_idx[T_TOK];                     // normalized token_batch_idx

// ---------------------------------------------------------------------------
// K_idx: normalize token_batch_idx to int32, whatever dtype the harness ships.
// int64 layout: odd 32-bit words are all zero high-words (values 0..15).
// int32 layout: odd words carry real (mostly nonzero) indices.
// One block, 256 threads, two passes with a shared flag. Deterministic.
// ---------------------------------------------------------------------------
__global__ __launch_bounds__(256) void k_idx_normalize(const int* __restrict__ raw)
{
    __shared__ int s_odd_or;
    if (threadIdx.x == 0) s_odd_or = 0;
    __syncthreads();

    int local_or = 0;
    for (int i = threadIdx.x; i < T_TOK; i += 256)
        local_or |= raw[2 * i + 1];           // odd words of first 2048 pairs
    // warp-reduce then atomic into shared
    #pragma unroll
    for (int off = 16; off > 0; off >>= 1)
        local_or |= __shfl_xor_sync(0xFFFFFFFFu, local_or, off);
    if ((threadIdx.x & 31) == 0) atomicOr(&s_odd_or, local_or);
    __syncthreads();

    const bool is64 = (s_odd_or == 0);
    for (int i = threadIdx.x; i < T_TOK; i += 256) {
        int v = is64 ? raw[2 * i] : raw[i];
        g_idx[i] = min(max(v, 0), B_SAMP - 1);
    }
}

// ---------------------------------------------------------------------------
// K0: partial vision GEMM  V1part[s][b][n] = sum_{k in chunk s} vis[b][k]*W1[k][n]
// grid: (FF/256, KSPLIT), block 256
// ---------------------------------------------------------------------------
__global__ __launch_bounds__(256) void k0_vis_partial(
    const float* __restrict__ visf,   // [16][32768]
    const float* __restrict__ W1)     // [36864][1024], rows 0..32767 = vision
{
    __shared__ float sv[B_SAMP][KCHUNK];   // 32 KB
    const int tid = threadIdx.x;
    const int n  = blockIdx.x * 256 + tid;
    const int k0 = blockIdx.y * KCHUNK;

    // stage vis chunk: 16*512 floats = 2048 float4, 8 per thread
    #pragma unroll
    for (int s = tid; s < B_SAMP * (KCHUNK / 4); s += 256) {
        int b = s / (KCHUNK / 4);
        int c = s % (KCHUNK / 4);
        ((float4*)&sv[b][0])[c] =
            ((const float4*)(visf + (size_t)b * VIS_K + k0))[c];
    }
    __syncthreads();

    float acc[B_SAMP];
    #pragma unroll
    for (int b = 0; b < B_SAMP; b++) acc[b] = 0.f;

    const float* Wc = W1 + (size_t)k0 * FF + n;
    for (int kk = 0; kk < KCHUNK; kk += 4) {
        float w0 = Wc[(size_t)(kk + 0) * FF];
        float w1 = Wc[(size_t)(kk + 1) * FF];
        float w2 = Wc[(size_t)(kk + 2) * FF];
        float w3 = Wc[(size_t)(kk + 3) * FF];
        #pragma unroll
        for (int b = 0; b < B_SAMP; b++) {
            float4 v = *(const float4*)&sv[b][kk];
            acc[b] += v.x * w0 + v.y * w1 + v.z * w2 + v.w * w3;
        }
    }

    float* p = g_V1part + (size_t)blockIdx.y * (B_SAMP * FF) + n;
    #pragma unroll
    for (int b = 0; b < B_SAMP; b++) p[b * FF] = acc[b];
}

// K0b: reduce partials -> g_V1
__global__ __launch_bounds__(256) void k0_reduce() {
    int i = blockIdx.x * 256 + threadIdx.x;   // 16384 total
    float s = 0.f;
    #pragma unroll 8
    for (int p = 0; p < KSPLIT; p++) s += g_V1part[p * (B_SAMP * FF) + i];
    g_V1[i] = s;
}

// ---------------------------------------------------------------------------
// tf32 wmma GEMM: C[M,N] = act(A[M,K] @ W[K,N] + bias [+ V1[g_idx[row]]])
// BM=128, BN=64, BK=32, 8 warps (4x2), warp tile 32x32 (2x2 m16n16k8 frags)
// ---------------------------------------------------------------------------
#define AS_LD 36
#define BS_LD 68

template<bool FUSE_V, bool RELU>
__global__ __launch_bounds__(256) void gemm_tf32(
    const float* __restrict__ A,
    const float* __restrict__ W,
    const float* __restrict__ bias,
    const float* __restrict__ vadd,
    float* __restrict__ C,
    int M, int N, int K)
{
    __shared__ float smem[8192];           // 32 KB, reused for epilogue
    float* As = smem;                      // [128][36]
    float* Bs = smem + 128 * AS_LD;        // [32][68]

    const int tid  = threadIdx.x;
    const int warp = tid >> 5;
    const int wm   = warp & 3;             // 0..3
    const int wn   = warp >> 2;            // 0..1
    const int bm   = blockIdx.y * 128;
    const int bn   = blockIdx.x * 64;

    wmma::fragment<wmma::accumulator, 16, 16, 8, float> acc[2][2];
    #pragma unroll
    for (int i = 0; i < 2; i++)
        #pragma unroll
        for (int j = 0; j < 2; j++)
            wmma::fill_fragment(acc[i][j], 0.0f);

    for (int k0 = 0; k0 < K; k0 += 32) {
        // A tile 128x32 = 1024 float4 loads, 4 per thread
        #pragma unroll
        for (int it = 0; it < 4; it++) {
            int s = tid + it * 256;
            int r = s >> 3;
            int c = (s & 7) * 4;
            float4 v = *(const float4*)(A + (size_t)(bm + r) * K + k0 + c);
            *(float4*)&As[r * AS_LD + c] = v;
        }
        // B tile 32x64 = 512 float4 loads, 2 per thread
        #pragma unroll
        for (int it = 0; it < 2; it++) {
            int s = tid + it * 256;
            int r = s >> 4;
            int c = (s & 15) * 4;
            float4 v = *(const float4*)(W + (size_t)(k0 + r) * N + bn + c);
            *(float4*)&Bs[r * BS_LD + c] = v;
        }
        __syncthreads();

        #pragma unroll
        for (int kk = 0; kk < 32; kk += 8) {
            wmma::fragment<wmma::matrix_a, 16, 16, 8,
                           wmma::precision::tf32, wmma::row_major> af[2];
            wmma::fragment<wmma::matrix_b, 16, 16, 8,
                           wmma::precision::tf32, wmma::row_major> bf[2];
            #pragma unroll
            for (int i = 0; i < 2; i++) {
                wmma::load_matrix_sync(af[i],
                    &As[(wm * 32 + i * 16) * AS_LD + kk], AS_LD);
                #pragma unroll
                for (int t = 0; t < af[i].num_elements; t++)
                    af[i].x[t] = wmma::__float_to_tf32(af[i].x[t]);
            }
            #pragma unroll
            for (int j = 0; j < 2; j++) {
                wmma::load_matrix_sync(bf[j],
                    &Bs[kk * BS_LD + wn * 32 + j * 16], BS_LD);
                #pragma unroll
                for (int t = 0; t < bf[j].num_elements; t++)
                    bf[j].x[t] = wmma::__float_to_tf32(bf[j].x[t]);
            }
            #pragma unroll
            for (int i = 0; i < 2; i++)
                #pragma unroll
                for (int j = 0; j < 2; j++)
                    wmma::mma_sync(acc[i][j], af[i], bf[j], acc[i][j]);
        }
        __syncthreads();
    }

    // Epilogue: stage 128x64 into smem, then fused bias/gather/relu store
    float* Cs = smem;                      // [128][64]
    #pragma unroll
    for (int i = 0; i < 2; i++)
        #pragma unroll
        for (int j = 0; j < 2; j++)
            wmma::store_matrix_sync(&Cs[(wm * 32 + i * 16) * 64 + wn * 32 + j * 16],
                                    acc[i][j], 64, wmma::mem_row_major);
    __syncthreads();

    #pragma unroll
    for (int it = 0; it < 8; it++) {
        int s = tid + it * 256;            // 2048 float4 slots
        int r = s >> 4;
        int c = (s & 15) * 4;
        float4 v = *(float4*)&Cs[r * 64 + c];
        int row = bm + r;
        int col = bn + c;
        float4 bb = *(const float4*)(bias + col);
        v.x += bb.x; v.y += bb.y; v.z += bb.z; v.w += bb.w;
        if (FUSE_V) {
            int bi = g_idx[row];               // already clamped to [0,15]
            float4 va = *(const float4*)(vadd + (size_t)bi * FF + col);
            v.x += va.x; v.y += va.y; v.z += va.z; v.w += va.w;
        }
        if (RELU) {
            v.x = fmaxf(v.x, 0.f); v.y = fmaxf(v.y, 0.f);
            v.z = fmaxf(v.z, 0.f); v.w = fmaxf(v.w, 0.f);
        }
        *(float4*)(C + (size_t)row * N + col) = v;
    }
}

// ---------------------------------------------------------------------------
// K5: out[T,6] = H[T,1024] @ W5[1024,6] + b5  (one warp per token row)
// ---------------------------------------------------------------------------
__global__ __launch_bounds__(256) void k5_head(
    const float* __restrict__ H,
    const float* __restrict__ W5,
    const float* __restrict__ b5,
    float* __restrict__ out)
{
    int gw   = (blockIdx.x * blockDim.x + threadIdx.x) >> 5;
    int lane = threadIdx.x & 31;
    if (gw >= T_TOK) return;

    float acc[OUT_D] = {0.f, 0.f, 0.f, 0.f, 0.f, 0.f};
    const float* h = H + (size_t)gw * FF;
    for (int k = lane; k < FF; k += 32) {
        float hv = h[k];
        #pragma unroll
        for (int j = 0; j < OUT_D; j++)
            acc[j] += hv * W5[k * OUT_D + j];
    }
    #pragma unroll
    for (int j = 0; j < OUT_D; j++) {
        #pragma unroll
        for (int off = 16; off > 0; off >>= 1)
            acc[j] += __shfl_down_sync(0xFFFFFFFFu, acc[j], off);
    }
    if (lane == 0) {
        #pragma unroll
        for (int j = 0; j < OUT_D; j++)
            out[gw * OUT_D + j] = acc[j] + b5[j];
    }
}

// ---------------------------------------------------------------------------
extern "C" void kernel_launch(void* const* d_in, const int* in_sizes, int n_in,
                              void* d_out, int out_size)
{
    const float* grd  = (const float*)d_in[0];
    const float* visf = (const float*)d_in[1];
    const int*   tbi  = (const int*)d_in[2];   // dtype normalized on-device
    const float* W1   = (const float*)d_in[3];
    const float* b1   = (const float*)d_in[4];
    const float* W2   = (const float*)d_in[5];
    const float* b2   = (const float*)d_in[6];
    const float* W3   = (const float*)d_in[7];
    const float* b3   = (const float*)d_in[8];
    const float* W4   = (const float*)d_in[9];
    const float* b4   = (const float*)d_in[10];
    const float* W5   = (const float*)d_in[11];
    const float* b5   = (const float*)d_in[12];
    float*       out  = (float*)d_out;

    float *V1, *HA, *HB;
    cudaGetSymbolAddress((void**)&V1, g_V1);
    cudaGetSymbolAddress((void**)&HA, g_HA);
    cudaGetSymbolAddress((void**)&HB, g_HB);

    // Normalize token_batch_idx (handles int32 or int64 harness layout)
    k_idx_normalize<<<1, 256>>>(tbi);

    // Vision contribution: V1[16][1024] = vis_flat @ W1[0:32768]
    k0_vis_partial<<<dim3(FF / 256, KSPLIT), 256>>>(visf, W1);
    k0_reduce<<<(B_SAMP * FF) / 256, 256>>>();

    dim3 g1(FF / 64, T_TOK / 128);
    // Layer 1: relu(grd @ W1_lm + V1[idx] + b1)
    gemm_tf32<true, true><<<g1, 256>>>(grd, W1 + (size_t)VIS_K * FF, b1,
                                       V1, HA, T_TOK, FF, LM_DIM);
    // Layers 2-4
    gemm_tf32<false, true><<<g1, 256>>>(HA, W2, b2, nullptr, HB,
                                        T_TOK, FF, FF);
    gemm_tf32<false, true><<<g1, 256>>>(HB, W3, b3, nullptr, HA,
                                        T_TOK, FF, FF);
    gemm_tf32<false, true><<<g1, 256>>>(HA, W4, b4, nullptr, HB,
                                        T_TOK, FF, FF);
    // Head
    k5_head<<<(T_TOK * 32) / 256, 256>>>(HB, W5, b5, out);
}

// round 11
// speedup vs baseline: 1.1960x; 1.1960x over previous
#include <cstdint>
#include <cuda_runtime.h>
#include <cuda_bf16.h>
#include <mma.h>

using namespace nvcuda;

// Problem constants
#define T_TOK   2048
#define LM_DIM  4096
#define V_DIM   1024
#define N_V     32
#define FF      1024
#define VIS_K   (V_DIM * N_V)        // 32768
#define IN_DIM  (VIS_K + LM_DIM)     // 36864
#define B_SAMP  16
#define OUT_D   6

#define KSPLIT  128
#define KCHUNK  (VIS_K / KSPLIT)     // 256

// Scratch (static device globals: allocation-free rule)
__device__ float g_V1part[KSPLIT * B_SAMP * FF];   // 8 MB
__device__ float g_V1[B_SAMP * FF];                // 64 KB
__device__ float g_HA[T_TOK * FF];                 // 8 MB
__device__ float g_HB[T_TOK * FF];                 // 8 MB
__device__ int   g_idx[T_TOK];                     // normalized token_batch_idx

// ---------------------------------------------------------------------------
// K_idx: normalize token_batch_idx to int32 (verified working in R4)
// ---------------------------------------------------------------------------
__global__ __launch_bounds__(256) void k_idx_normalize(const int* __restrict__ raw)
{
    __shared__ int s_odd_or;
    if (threadIdx.x == 0) s_odd_or = 0;
    __syncthreads();

    int local_or = 0;
    for (int i = threadIdx.x; i < T_TOK; i += 256)
        local_or |= raw[2 * i + 1];
    #pragma unroll
    for (int off = 16; off > 0; off >>= 1)
        local_or |= __shfl_xor_sync(0xFFFFFFFFu, local_or, off);
    if ((threadIdx.x & 31) == 0) atomicOr(&s_odd_or, local_or);
    __syncthreads();

    const bool is64 = (s_odd_or == 0);
    for (int i = threadIdx.x; i < T_TOK; i += 256) {
        int v = is64 ? raw[2 * i] : raw[i];
        g_idx[i] = min(max(v, 0), B_SAMP - 1);
    }
}

// ---------------------------------------------------------------------------
// K0: partial vision GEMM (streaming 134MB of W1_vis; KSPLIT=128 for MLP)
// grid: (FF/256, KSPLIT), block 256
// ---------------------------------------------------------------------------
__global__ __launch_bounds__(256) void k0_vis_partial(
    const float* __restrict__ visf,
    const float* __restrict__ W1)
{
    __shared__ float sv[B_SAMP][KCHUNK];   // 16 KB
    const int tid = threadIdx.x;
    const int n  = blockIdx.x * 256 + tid;
    const int k0 = blockIdx.y * KCHUNK;

    #pragma unroll
    for (int s = tid; s < B_SAMP * (KCHUNK / 4); s += 256) {
        int b = s / (KCHUNK / 4);
        int c = s % (KCHUNK / 4);
        ((float4*)&sv[b][0])[c] =
            ((const float4*)(visf + (size_t)b * VIS_K + k0))[c];
    }
    __syncthreads();

    float acc[B_SAMP];
    #pragma unroll
    for (int b = 0; b < B_SAMP; b++) acc[b] = 0.f;

    const float* Wc = W1 + (size_t)k0 * FF + n;
    for (int kk = 0; kk < KCHUNK; kk += 4) {
        float w0 = Wc[(size_t)(kk + 0) * FF];
        float w1 = Wc[(size_t)(kk + 1) * FF];
        float w2 = Wc[(size_t)(kk + 2) * FF];
        float w3 = Wc[(size_t)(kk + 3) * FF];
        #pragma unroll
        for (int b = 0; b < B_SAMP; b++) {
            float4 v = *(const float4*)&sv[b][kk];
            acc[b] += v.x * w0 + v.y * w1 + v.z * w2 + v.w * w3;
        }
    }

    float* p = g_V1part + (size_t)blockIdx.y * (B_SAMP * FF) + n;
    #pragma unroll
    for (int b = 0; b < B_SAMP; b++) p[b * FF] = acc[b];
}

__global__ __launch_bounds__(256) void k0_reduce() {
    int i = blockIdx.x * 256 + threadIdx.x;
    float s = 0.f;
    #pragma unroll 8
    for (int p = 0; p < KSPLIT; p++) s += g_V1part[p * (B_SAMP * FF) + i];
    g_V1[i] = s;
}

// ---------------------------------------------------------------------------
// tf32 wmma GEMM with 2-stage cp.async pipeline.
// BM=128, BN=64, BK=32, 8 warps (4x2), warp tile 32x32.
// Dynamic smem: 2 stages * (128*36 + 32*68) floats = 54272 B.
// ---------------------------------------------------------------------------
#define AS_LD 36
#define BS_LD 68
#define ASZ   (128 * AS_LD)          // 4608 floats
#define BSZ   (32 * BS_LD)           // 2176 floats
#define STG   (ASZ + BSZ)            // 6784 floats per stage
#define GEMM_SMEM_BYTES (2 * STG * 4)  // 54272

__device__ __forceinline__ void cp_async16(float* smem_dst, const float* gmem_src) {
    unsigned int s = (unsigned int)__cvta_generic_to_shared(smem_dst);
    asm volatile("cp.async.cg.shared.global [%0], [%1], 16;\n" :: "r"(s), "l"(gmem_src));
}
__device__ __forceinline__ void cp_commit() {
    asm volatile("cp.async.commit_group;\n");
}
template<int N>
__device__ __forceinline__ void cp_wait() {
    asm volatile("cp.async.wait_group %0;\n" :: "n"(N));
}

template<bool FUSE_V, bool RELU>
__global__ __launch_bounds__(256, 2) void gemm_tf32(
    const float* __restrict__ A,
    const float* __restrict__ W,
    const float* __restrict__ bias,
    const float* __restrict__ vadd,
    float* __restrict__ C,
    int M, int N, int K)
{
    extern __shared__ float smem[];

    const int tid  = threadIdx.x;
    const int warp = tid >> 5;
    const int wm   = warp & 3;
    const int wn   = warp >> 2;
    const int bm   = blockIdx.y * 128;
    const int bn   = blockIdx.x * 64;

    // per-thread load coordinates (constant across iterations)
    const int ar = tid >> 3;            // + it*32 rows
    const int ac = (tid & 7) * 4;
    const int br = tid >> 4;            // + it*16 rows
    const int bc = (tid & 15) * 4;

    wmma::fragment<wmma::accumulator, 16, 16, 8, float> acc[2][2];
    #pragma unroll
    for (int i = 0; i < 2; i++)
        #pragma unroll
        for (int j = 0; j < 2; j++)
            wmma::fill_fragment(acc[i][j], 0.0f);

    const int nk = K >> 5;   // K / 32

    // ---- async tile loader ----
    auto issue_tile = [&](int stage, int kt) {
        float* As = smem + stage * STG;
        float* Bs = As + ASZ;
        const int k0 = kt << 5;
        #pragma unroll
        for (int it = 0; it < 4; it++) {
            int r = ar + it * 32;
            cp_async16(&As[r * AS_LD + ac],
                       A + (size_t)(bm + r) * K + k0 + ac);
        }
        #pragma unroll
        for (int it = 0; it < 2; it++) {
            int r = br + it * 16;
            cp_async16(&Bs[r * BS_LD + bc],
                       W + (size_t)(k0 + r) * N + bn + bc);
        }
    };

    // prologue: stage 0 <- tile 0
    issue_tile(0, 0);
    cp_commit();

    for (int kt = 0; kt < nk; kt++) {
        const int cur = kt & 1;
        if (kt + 1 < nk) {
            issue_tile(cur ^ 1, kt + 1);
            cp_commit();
            cp_wait<1>();          // tile kt complete; kt+1 may be in flight
        } else {
            cp_commit();           // empty group keeps accounting simple
            cp_wait<0>();
        }
        __syncthreads();

        float* As = smem + cur * STG;
        float* Bs = As + ASZ;

        #pragma unroll
        for (int kk = 0; kk < 32; kk += 8) {
            wmma::fragment<wmma::matrix_a, 16, 16, 8,
                           wmma::precision::tf32, wmma::row_major> af[2];
            wmma::fragment<wmma::matrix_b, 16, 16, 8,
                           wmma::precision::tf32, wmma::row_major> bf[2];
            #pragma unroll
            for (int i = 0; i < 2; i++) {
                wmma::load_matrix_sync(af[i],
                    &As[(wm * 32 + i * 16) * AS_LD + kk], AS_LD);
                #pragma unroll
                for (int t = 0; t < af[i].num_elements; t++)
                    af[i].x[t] = wmma::__float_to_tf32(af[i].x[t]);
            }
            #pragma unroll
            for (int j = 0; j < 2; j++) {
                wmma::load_matrix_sync(bf[j],
                    &Bs[kk * BS_LD + wn * 32 + j * 16], BS_LD);
                #pragma unroll
                for (int t = 0; t < bf[j].num_elements; t++)
                    bf[j].x[t] = wmma::__float_to_tf32(bf[j].x[t]);
            }
            #pragma unroll
            for (int i = 0; i < 2; i++)
                #pragma unroll
                for (int j = 0; j < 2; j++)
                    wmma::mma_sync(acc[i][j], af[i], bf[j], acc[i][j]);
        }
        __syncthreads();   // protect buffer 'cur' before next-next load overwrites it
    }

    // Epilogue: stage 128x64 into smem, then fused bias/gather/relu store
    float* Cs = smem;
    #pragma unroll
    for (int i = 0; i < 2; i++)
        #pragma unroll
        for (int j = 0; j < 2; j++)
            wmma::store_matrix_sync(&Cs[(wm * 32 + i * 16) * 64 + wn * 32 + j * 16],
                                    acc[i][j], 64, wmma::mem_row_major);
    __syncthreads();

    #pragma unroll
    for (int it = 0; it < 8; it++) {
        int s = tid + it * 256;
        int r = s >> 4;
        int c = (s & 15) * 4;
        float4 v = *(float4*)&Cs[r * 64 + c];
        int row = bm + r;
        int col = bn + c;
        float4 bb = *(const float4*)(bias + col);
        v.x += bb.x; v.y += bb.y; v.z += bb.z; v.w += bb.w;
        if (FUSE_V) {
            int bi = g_idx[row];
            float4 va = *(const float4*)(vadd + (size_t)bi * FF + col);
            v.x += va.x; v.y += va.y; v.z += va.z; v.w += va.w;
        }
        if (RELU) {
            v.x = fmaxf(v.x, 0.f); v.y = fmaxf(v.y, 0.f);
            v.z = fmaxf(v.z, 0.f); v.w = fmaxf(v.w, 0.f);
        }
        *(float4*)(C + (size_t)row * N + col) = v;
    }
}

// ---------------------------------------------------------------------------
// K5: out[T,6] = H[T,1024] @ W5[1024,6] + b5
// ---------------------------------------------------------------------------
__global__ __launch_bounds__(256) void k5_head(
    const float* __restrict__ H,
    const float* __restrict__ W5,
    const float* __restrict__ b5,
    float* __restrict__ out)
{
    int gw   = (blockIdx.x * blockDim.x + threadIdx.x) >> 5;
    int lane = threadIdx.x & 31;
    if (gw >= T_TOK) return;

    float acc[OUT_D] = {0.f, 0.f, 0.f, 0.f, 0.f, 0.f};
    const float* h = H + (size_t)gw * FF;
    for (int k = lane; k < FF; k += 32) {
        float hv = h[k];
        #pragma unroll
        for (int j = 0; j < OUT_D; j++)
            acc[j] += hv * W5[k * OUT_D + j];
    }
    #pragma unroll
    for (int j = 0; j < OUT_D; j++) {
        #pragma unroll
        for (int off = 16; off > 0; off >>= 1)
            acc[j] += __shfl_down_sync(0xFFFFFFFFu, acc[j], off);
    }
    if (lane == 0) {
        #pragma unroll
        for (int j = 0; j < OUT_D; j++)
            out[gw * OUT_D + j] = acc[j] + b5[j];
    }
}

// ---------------------------------------------------------------------------
extern "C" void kernel_launch(void* const* d_in, const int* in_sizes, int n_in,
                              void* d_out, int out_size)
{
    const float* grd  = (const float*)d_in[0];
    const float* visf = (const float*)d_in[1];
    const int*   tbi  = (const int*)d_in[2];
    const float* W1   = (const float*)d_in[3];
    const float* b1   = (const float*)d_in[4];
    const float* W2   = (const float*)d_in[5];
    const float* b2   = (const float*)d_in[6];
    const float* W3   = (const float*)d_in[7];
    const float* b3   = (const float*)d_in[8];
    const float* W4   = (const float*)d_in[9];
    const float* b4   = (const float*)d_in[10];
    const float* W5   = (const float*)d_in[11];
    const float* b5   = (const float*)d_in[12];
    float*       out  = (float*)d_out;

    float *V1, *HA, *HB;
    cudaGetSymbolAddress((void**)&V1, g_V1);
    cudaGetSymbolAddress((void**)&HA, g_HA);
    cudaGetSymbolAddress((void**)&HB, g_HB);

    // one-time (idempotent) opt-in to >48KB dynamic smem
    cudaFuncSetAttribute(gemm_tf32<true, true>,
                         cudaFuncAttributeMaxDynamicSharedMemorySize, GEMM_SMEM_BYTES);
    cudaFuncSetAttribute(gemm_tf32<false, true>,
                         cudaFuncAttributeMaxDynamicSharedMemorySize, GEMM_SMEM_BYTES);

    k_idx_normalize<<<1, 256>>>(tbi);

    k0_vis_partial<<<dim3(FF / 256, KSPLIT), 256>>>(visf, W1);
    k0_reduce<<<(B_SAMP * FF) / 256, 256>>>();

    dim3 g1(FF / 64, T_TOK / 128);
    gemm_tf32<true, true><<<g1, 256, GEMM_SMEM_BYTES>>>(
        grd, W1 + (size_t)VIS_K * FF, b1, V1, HA, T_TOK, FF, LM_DIM);
    gemm_tf32<false, true><<<g1, 256, GEMM_SMEM_BYTES>>>(
        HA, W2, b2, nullptr, HB, T_TOK, FF, FF);
    gemm_tf32<false, true><<<g1, 256, GEMM_SMEM_BYTES>>>(
        HB, W3, b3, nullptr, HA, T_TOK, FF, FF);
    gemm_tf32<false, true><<<g1, 256, GEMM_SMEM_BYTES>>>(
        HA, W4, b4, nullptr, HB, T_TOK, FF, FF);
    k5_head<<<(T_TOK * 32) / 256, 256>>>(HB, W5, b5, out);
}